// round 13
// baseline (speedup 1.0000x reference)
#include <cuda_runtime.h>
#include <cuda_fp16.h>
#include <cstdint>
#include <cstddef>

#define H      128
#define EMB    64
#define LAYERS 3
#define N_MAX  100000
#define E_MAX  1600000
#define G_MAX  1024

// ---------------- scratch (device globals; no allocation allowed) ----------------
__device__ float g_P [(size_t)N_MAX * H];   // pre-BN activations (fp32)
__device__ float g_HW[(size_t)N_MAX * H];   // layer GEMM output; stored as fp16 (reused buffer)
__device__ int   g_deg[N_MAX];
__device__ float g_dinv[N_MAX];
__device__ int   g_rowptr[N_MAX + 1];
__device__ int   g_cursor[N_MAX];
__device__ int   g_csrsrc[E_MAX];
__device__ float g_csrw[E_MAX];
__device__ int   g_chunksum[128];
__device__ int   g_chunkoff[128];
__device__ float g_bnsum[LAYERS * H];
__device__ float g_bnsq [LAYERS * H];
__device__ float g_ts[(LAYERS + 1) * H];
__device__ float g_tt[(LAYERS + 1) * H];
__device__ int   g_aggdone[LAYERS];         // last-block counters for fused bnfin
__device__ int   g_gstart[G_MAX + 1];

// ---------------- init ----------------
__global__ void k_init(int Nn) {
    int i = blockIdx.x * blockDim.x + threadIdx.x;
    if (i < Nn) { g_deg[i] = 0; g_cursor[i] = 0; }
    if (i < LAYERS * H) { g_bnsum[i] = 0.0f; g_bnsq[i] = 0.0f; }
    if (i < LAYERS) g_aggdone[i] = 0;
}

// ---------------- degree count / dinv ----------------
__global__ void k_count(const int* __restrict__ ei, int E) {
    int e = blockIdx.x * blockDim.x + threadIdx.x;
    if (e < E) atomicAdd(&g_deg[ei[E + e]], 1);
}

__global__ void k_dinv(int Nn) {
    int i = blockIdx.x * blockDim.x + threadIdx.x;
    if (i < Nn) g_dinv[i] = rsqrtf((float)g_deg[i] + 1.0f);
}

// ---------------- exclusive scan (1024-elem chunks) ----------------
__global__ void k_chunksum(int Nn) {
    __shared__ int sm[256];
    int base = blockIdx.x * 1024;
    int s = 0;
    for (int j = threadIdx.x; j < 1024; j += 256) {
        int i = base + j;
        if (i < Nn) s += g_deg[i];
    }
    sm[threadIdx.x] = s; __syncthreads();
    for (int d = 128; d > 0; d >>= 1) {
        if (threadIdx.x < d) sm[threadIdx.x] += sm[threadIdx.x + d];
        __syncthreads();
    }
    if (threadIdx.x == 0) g_chunksum[blockIdx.x] = sm[0];
}

__global__ void k_scanchunks(int nb) {
    if (threadIdx.x == 0) {
        int acc = 0;
        for (int b = 0; b < nb; b++) { g_chunkoff[b] = acc; acc += g_chunksum[b]; }
    }
}

__global__ void k_scanlocal(int Nn, int E) {
    __shared__ int sm[1024];
    int i = blockIdx.x * 1024 + threadIdx.x;
    int v = (i < Nn) ? g_deg[i] : 0;
    sm[threadIdx.x] = v; __syncthreads();
    for (int d = 1; d < 1024; d <<= 1) {
        int x = (threadIdx.x >= d) ? sm[threadIdx.x - d] : 0;
        __syncthreads();
        sm[threadIdx.x] += x;
        __syncthreads();
    }
    if (i < Nn) g_rowptr[i] = g_chunkoff[blockIdx.x] + sm[threadIdx.x] - v;  // exclusive
    if (i == 0) g_rowptr[Nn] = E;
}

// ---------------- CSR scatter ----------------
__global__ void k_scatter(const int* __restrict__ ei, int E) {
    int e = blockIdx.x * blockDim.x + threadIdx.x;
    if (e >= E) return;
    int s = ei[e], d = ei[E + e];
    int pos = g_rowptr[d] + atomicAdd(&g_cursor[d], 1);
    g_csrsrc[pos] = s;
    g_csrw[pos]   = g_dinv[s] * g_dinv[d];
}

// ---------------- graph boundary (batch is sorted) ----------------
__global__ void k_gstart(const int* __restrict__ batch, int Nn, int G) {
    int g = blockIdx.x * blockDim.x + threadIdx.x;
    if (g > G) return;
    if (g == G) { g_gstart[G] = Nn; return; }
    int lo = 0, hi = Nn;
    while (lo < hi) {
        int mid = (lo + hi) >> 1;
        if (batch[mid] < g) lo = mid + 1; else hi = mid;
    }
    g_gstart[g] = lo;
}

// ---------------- packed f32x2 helpers ----------------
__device__ __forceinline__ void fma_f32x2(unsigned long long& acc,
                                          unsigned long long a,
                                          unsigned long long b) {
    asm("fma.rn.f32x2 %0, %1, %2, %0;" : "+l"(acc) : "l"(a), "l"(b));
}
__device__ __forceinline__ unsigned long long dup_f32(float v) {
    unsigned long long r;
    asm("mov.b64 %0, {%1, %1};" : "=l"(r) : "f"(v));
    return r;
}

// ---------------- SGEMM (FFMA2, 16x8 tile, 128 thr, 2 CTAs/SM, double-buffered) ---
// Block tile M=128 x N=128, 128 threads.  Thread: 16 M-rows (8 packed pairs) x 8 N.
// Double-buffered smem: ONE __syncthreads per k-tile (stage writes idle buffer).
// TRANSFORM: 0 = identity (+bias), 1 = BN(s,t)+ReLU, 2 = plain ReLU
// OUTHALF=1: C stored as fp16 for the aggregation gather
#define MT 128
template <int TRANSFORM, int OUTHALF>
__global__ void __launch_bounds__(128, 2) k_gemm(
    const float* __restrict__ A, const float* __restrict__ B, void* __restrict__ C,
    int M, const float* __restrict__ s, const float* __restrict__ t,
    const float* __restrict__ bias)
{
    __shared__ float As[2][16][MT + 8];   // [buf][k][m]
    __shared__ float Bs[2][16][128];      // [buf][k][n]
    const int tid = threadIdx.x;
    const int tx = tid & 15, ty = tid >> 4;
    const int m0 = blockIdx.x * MT;

    const int arow0 = tid >> 2, ac4 = (tid & 3) * 4;   // A: 4 pieces, rows arow0 + l*32
    const int brow0 = tid >> 5, bcc = (tid & 31) * 4;  // B: 4 pieces, rows brow0 + l*4

    float4 sv = make_float4(0.f, 0.f, 0.f, 0.f);
    float4 tv = make_float4(0.f, 0.f, 0.f, 0.f);

    unsigned long long acc2[8][8];
#pragma unroll
    for (int i = 0; i < 8; i++)
#pragma unroll
        for (int j = 0; j < 8; j++) acc2[i][j] = 0ULL;

    float4 pa[4], pb[4];

    // ---- load tile kt=0 into regs ----
#pragma unroll
    for (int l = 0; l < 4; l++) {
        int gm = m0 + arow0 + l * 32;
        pa[l] = (gm < M) ? *(const float4*)(A + (size_t)gm * H + ac4)
                         : make_float4(0.f, 0.f, 0.f, 0.f);
    }
#pragma unroll
    for (int l = 0; l < 4; l++)
        pb[l] = *(const float4*)(B + (size_t)(brow0 + l * 4) * H + bcc);

    // stage tile 0 into buffer 0
    {
        if (TRANSFORM == 1) {
            sv = *(const float4*)(s + ac4);
            tv = *(const float4*)(t + ac4);
        }
#pragma unroll
        for (int l = 0; l < 4; l++) {
            float4 v = pa[l];
            if (TRANSFORM == 1) {
                v.x = fmaxf(fmaf(v.x, sv.x, tv.x), 0.f);
                v.y = fmaxf(fmaf(v.y, sv.y, tv.y), 0.f);
                v.z = fmaxf(fmaf(v.z, sv.z, tv.z), 0.f);
                v.w = fmaxf(fmaf(v.w, sv.w, tv.w), 0.f);
            } else if (TRANSFORM == 2) {
                v.x = fmaxf(v.x, 0.f); v.y = fmaxf(v.y, 0.f);
                v.z = fmaxf(v.z, 0.f); v.w = fmaxf(v.w, 0.f);
            }
            int row = arow0 + l * 32;
            As[0][ac4 + 0][row] = v.x; As[0][ac4 + 1][row] = v.y;
            As[0][ac4 + 2][row] = v.z; As[0][ac4 + 3][row] = v.w;
        }
#pragma unroll
        for (int l = 0; l < 4; l++)
            *(float4*)(&Bs[0][brow0 + l * 4][bcc]) = pb[l];
    }
    __syncthreads();

#pragma unroll
    for (int it = 0; it < 8; it++) {
        const int cur = it & 1, nxt = cur ^ 1;
        const int ktn = (it + 1) * 16;
        // ---- prefetch tile it+1 (LDGs in flight during compute) ----
        if (it < 7) {
#pragma unroll
            for (int l = 0; l < 4; l++) {
                int gm = m0 + arow0 + l * 32;
                pa[l] = (gm < M) ? *(const float4*)(A + (size_t)gm * H + ktn + ac4)
                                 : make_float4(0.f, 0.f, 0.f, 0.f);
            }
#pragma unroll
            for (int l = 0; l < 4; l++)
                pb[l] = *(const float4*)(B + (size_t)(ktn + brow0 + l * 4) * H + bcc);
        }
        // ---- compute tile it from buffer cur ----
#pragma unroll
        for (int k = 0; k < 16; k++) {
            unsigned long long a2[8];
            const float* Ak = &As[cur][k][ty * 16];
            const ulonglong2 p0 = *(const ulonglong2*)(Ak);
            const ulonglong2 p1 = *(const ulonglong2*)(Ak + 4);
            const ulonglong2 p2 = *(const ulonglong2*)(Ak + 8);
            const ulonglong2 p3 = *(const ulonglong2*)(Ak + 12);
            a2[0] = p0.x; a2[1] = p0.y; a2[2] = p1.x; a2[3] = p1.y;
            a2[4] = p2.x; a2[5] = p2.y; a2[6] = p3.x; a2[7] = p3.y;
            float b[8];
            *(float4*)(b)     = *(const float4*)(&Bs[cur][k][tx * 8]);
            *(float4*)(b + 4) = *(const float4*)(&Bs[cur][k][tx * 8 + 4]);
            unsigned long long bd[8];
#pragma unroll
            for (int j = 0; j < 8; j++) bd[j] = dup_f32(b[j]);
#pragma unroll
            for (int i = 0; i < 8; i++)
#pragma unroll
                for (int j = 0; j < 8; j++)
                    fma_f32x2(acc2[i][j], a2[i], bd[j]);
        }
        // ---- stage prefetched tile into idle buffer (no barrier needed first) ----
        if (it < 7) {
            const int kg = ktn + ac4;
            if (TRANSFORM == 1) {
                sv = *(const float4*)(s + kg);
                tv = *(const float4*)(t + kg);
            }
#pragma unroll
            for (int l = 0; l < 4; l++) {
                float4 v = pa[l];
                if (TRANSFORM == 1) {
                    v.x = fmaxf(fmaf(v.x, sv.x, tv.x), 0.f);
                    v.y = fmaxf(fmaf(v.y, sv.y, tv.y), 0.f);
                    v.z = fmaxf(fmaf(v.z, sv.z, tv.z), 0.f);
                    v.w = fmaxf(fmaf(v.w, sv.w, tv.w), 0.f);
                } else if (TRANSFORM == 2) {
                    v.x = fmaxf(v.x, 0.f); v.y = fmaxf(v.y, 0.f);
                    v.z = fmaxf(v.z, 0.f); v.w = fmaxf(v.w, 0.f);
                }
                int row = arow0 + l * 32;
                As[nxt][ac4 + 0][row] = v.x; As[nxt][ac4 + 1][row] = v.y;
                As[nxt][ac4 + 2][row] = v.z; As[nxt][ac4 + 3][row] = v.w;
            }
#pragma unroll
            for (int l = 0; l < 4; l++)
                *(float4*)(&Bs[nxt][brow0 + l * 4][bcc]) = pb[l];
            __syncthreads();   // single barrier per k-tile
        }
    }

    // epilogue: acc2[i2][j] = rows (ty*16 + 2*i2, +1), col tx*8+j
#pragma unroll
    for (int i2 = 0; i2 < 8; i2++) {
        int gm = m0 + ty * 16 + 2 * i2;
        float lo[8], hi[8];
#pragma unroll
        for (int j = 0; j < 8; j++) {
            float2 p = *(float2*)(&acc2[i2][j]);
            lo[j] = p.x; hi[j] = p.y;
        }
        if (bias) {
#pragma unroll
            for (int j = 0; j < 8; j++) {
                float bj = bias[tx * 8 + j];
                lo[j] += bj; hi[j] += bj;
            }
        }
        if (OUTHALF) {
            __half* Ch = (__half*)C;
            __half2 hv[4];
            if (gm < M) {
#pragma unroll
                for (int j2 = 0; j2 < 4; j2++)
                    hv[j2] = __floats2half2_rn(lo[2 * j2], lo[2 * j2 + 1]);
                *(uint4*)(Ch + (size_t)gm * H + tx * 8) = *(uint4*)hv;
            }
            if (gm + 1 < M) {
#pragma unroll
                for (int j2 = 0; j2 < 4; j2++)
                    hv[j2] = __floats2half2_rn(hi[2 * j2], hi[2 * j2 + 1]);
                *(uint4*)(Ch + (size_t)(gm + 1) * H + tx * 8) = *(uint4*)hv;
            }
        } else {
            float* Cf = (float*)C;
            if (gm < M) {
                *(float4*)(Cf + (size_t)gm * H + tx * 8)     = *(float4*)(lo);
                *(float4*)(Cf + (size_t)gm * H + tx * 8 + 4) = *(float4*)(lo + 4);
            }
            if (gm + 1 < M) {
                *(float4*)(Cf + (size_t)(gm + 1) * H + tx * 8)     = *(float4*)(hi);
                *(float4*)(Cf + (size_t)(gm + 1) * H + tx * 8 + 4) = *(float4*)(hi + 4);
            }
        }
    }
}

// ---------------- edge aggregation + fused BN stats + fused BN finalize -----------
__global__ void __launch_bounds__(256) k_agg(
    const __half* __restrict__ HWh, const float* __restrict__ bias,
    float* __restrict__ OUT, int Nn, int layer,
    const float* __restrict__ gammas, const float* __restrict__ betas)
{
    __shared__ float s_sum[H], s_sq[H];
    const int tid  = threadIdx.x;
    const int lane = tid & 31;
    if (tid < H) { s_sum[tid] = 0.f; s_sq[tid] = 0.f; }
    __syncthreads();

    int w = (blockIdx.x * blockDim.x + tid) >> 5;
    if (w < Nn) {
        const uint2* hw2 = (const uint2*)HWh;      // 8B = 4 halves per lane
        int e0 = g_rowptr[w], e1 = g_rowptr[w + 1];
        float4 acc = make_float4(0.f, 0.f, 0.f, 0.f);
        int e = e0;
        for (; e + 4 <= e1; e += 4) {
            int   s0 = g_csrsrc[e],     s1 = g_csrsrc[e + 1];
            int   s2 = g_csrsrc[e + 2], s3 = g_csrsrc[e + 3];
            float w0 = g_csrw[e],       w1 = g_csrw[e + 1];
            float w2 = g_csrw[e + 2],   w3 = g_csrw[e + 3];
            uint2 u0 = hw2[(size_t)s0 * 32 + lane];
            uint2 u1 = hw2[(size_t)s1 * 32 + lane];
            uint2 u2 = hw2[(size_t)s2 * 32 + lane];
            uint2 u3 = hw2[(size_t)s3 * 32 + lane];
            float2 a0 = __half22float2(*(__half2*)&u0.x), b0 = __half22float2(*(__half2*)&u0.y);
            float2 a1 = __half22float2(*(__half2*)&u1.x), b1 = __half22float2(*(__half2*)&u1.y);
            float2 a2 = __half22float2(*(__half2*)&u2.x), b2 = __half22float2(*(__half2*)&u2.y);
            float2 a3 = __half22float2(*(__half2*)&u3.x), b3 = __half22float2(*(__half2*)&u3.y);
            acc.x = fmaf(w0, a0.x, fmaf(w1, a1.x, fmaf(w2, a2.x, fmaf(w3, a3.x, acc.x))));
            acc.y = fmaf(w0, a0.y, fmaf(w1, a1.y, fmaf(w2, a2.y, fmaf(w3, a3.y, acc.y))));
            acc.z = fmaf(w0, b0.x, fmaf(w1, b1.x, fmaf(w2, b2.x, fmaf(w3, b3.x, acc.z))));
            acc.w = fmaf(w0, b0.y, fmaf(w1, b1.y, fmaf(w2, b2.y, fmaf(w3, b3.y, acc.w))));
        }
        for (; e < e1; e++) {
            int   src = g_csrsrc[e];
            float wt  = g_csrw[e];
            uint2 u = hw2[(size_t)src * 32 + lane];
            float2 f0 = __half22float2(*(__half2*)&u.x);
            float2 f1 = __half22float2(*(__half2*)&u.y);
            acc.x = fmaf(wt, f0.x, acc.x);
            acc.y = fmaf(wt, f0.y, acc.y);
            acc.z = fmaf(wt, f1.x, acc.z);
            acc.w = fmaf(wt, f1.y, acc.w);
        }
        float di = g_dinv[w];
        float sn = di * di;                       // 1/deg (self-loop norm)
        uint2 su = hw2[(size_t)w * 32 + lane];
        float2 s0 = __half22float2(*(__half2*)&su.x);
        float2 s1 = __half22float2(*(__half2*)&su.y);
        acc.x = fmaf(sn, s0.x, acc.x) + bias[lane * 4 + 0];
        acc.y = fmaf(sn, s0.y, acc.y) + bias[lane * 4 + 1];
        acc.z = fmaf(sn, s1.x, acc.z) + bias[lane * 4 + 2];
        acc.w = fmaf(sn, s1.y, acc.w) + bias[lane * 4 + 3];
        ((float4*)OUT)[(size_t)w * 32 + lane] = acc;

        atomicAdd(&s_sum[lane * 4 + 0], acc.x);
        atomicAdd(&s_sum[lane * 4 + 1], acc.y);
        atomicAdd(&s_sum[lane * 4 + 2], acc.z);
        atomicAdd(&s_sum[lane * 4 + 3], acc.w);
        atomicAdd(&s_sq[lane * 4 + 0], acc.x * acc.x);
        atomicAdd(&s_sq[lane * 4 + 1], acc.y * acc.y);
        atomicAdd(&s_sq[lane * 4 + 2], acc.z * acc.z);
        atomicAdd(&s_sq[lane * 4 + 3], acc.w * acc.w);
    }
    __syncthreads();
    if (tid < H) {
        atomicAdd(&g_bnsum[layer * H + tid], s_sum[tid]);
        atomicAdd(&g_bnsq [layer * H + tid], s_sq[tid]);
    }

    // ---- last-block BN finalize (replaces k_bnfin launch) ----
    __shared__ int s_last;
    __threadfence();
    __syncthreads();
    if (tid == 0) {
        int prev = atomicAdd(&g_aggdone[layer], 1);
        s_last = (prev == gridDim.x - 1);
    }
    __syncthreads();
    if (s_last && tid < H) {
        float invN = 1.0f / (float)Nn;
        float mean = g_bnsum[layer * H + tid] * invN;
        float var  = g_bnsq [layer * H + tid] * invN - mean * mean;
        float inv  = rsqrtf(var + 1e-5f);
        float sc   = gammas[layer * H + tid] * inv;
        g_ts[(layer + 1) * H + tid] = sc;
        g_tt[(layer + 1) * H + tid] = betas[layer * H + tid] - mean * sc;
    }
}

// ---------------- fused pool + head MLP (256 thr: 2 row-groups per graph) ---------
__global__ void k_poolmlp(const float* __restrict__ P,
                          const float* __restrict__ W1, const float* __restrict__ b1,
                          const float* __restrict__ W2, const float* __restrict__ b2,
                          float* __restrict__ out) {
    __shared__ float p[H], t1[H], part[H];
    int g = blockIdx.x;
    int c = threadIdx.x & 127;
    int grp = threadIdx.x >> 7;                 // 0 or 1
    int a = g_gstart[g], b = g_gstart[g + 1];
    float sc = g_ts[LAYERS * H + c], tt = g_tt[LAYERS * H + c];
    float acc = 0.f;
    for (int r = a + grp; r < b; r += 2)
        acc += fmaxf(fmaf(P[(size_t)r * H + c], sc, tt), 0.f);
    if (grp == 1) part[c] = acc;
    __syncthreads();
    if (grp == 0) p[c] = (acc + part[c]) / fmaxf((float)(b - a), 1.0f);
    __syncthreads();

    if (grp == 0) {
        float h1 = b1[c];
#pragma unroll
        for (int k = 0; k < H; k++) h1 = fmaf(p[k], W1[k * H + c], h1);
        t1[c] = fmaxf(h1, 0.f);
    }
    __syncthreads();
    if (grp == 0 && c < EMB) {
        float o = b2[c];
#pragma unroll
        for (int k = 0; k < H; k++) o = fmaf(t1[k], W2[k * EMB + c], o);
        out[(size_t)g * EMB + c] = o;
    }
}

// ---------------- launch ----------------
extern "C" void kernel_launch(void* const* d_in, const int* in_sizes, int n_in,
                              void* d_out, int out_size)
{
    const float* x      = (const float*)d_in[0];
    const int*   ei     = (const int*)  d_in[1];
    const int*   batch  = (const int*)  d_in[2];
    const float* W_in   = (const float*)d_in[3];
    const float* b_in   = (const float*)d_in[4];
    const float* Ws     = (const float*)d_in[5];
    const float* bs     = (const float*)d_in[6];
    const float* gammas = (const float*)d_in[7];
    const float* betas  = (const float*)d_in[8];
    const float* W1     = (const float*)d_in[9];
    const float* b1     = (const float*)d_in[10];
    const float* W2     = (const float*)d_in[11];
    const float* b2     = (const float*)d_in[12];

    int Nn = in_sizes[0] / H;
    int E  = in_sizes[1] / 2;
    int G  = out_size / EMB;

    float *P, *ts, *tt;
    void* HWp;
    cudaGetSymbolAddress((void**)&P,   g_P);
    cudaGetSymbolAddress(&HWp,         g_HW);
    cudaGetSymbolAddress((void**)&ts,  g_ts);
    cudaGetSymbolAddress((void**)&tt,  g_tt);

    int mblocks = (Nn + MT - 1) / MT;
    int nb = (Nn + 1023) / 1024;

    // side stream + fork/join events (created once; capture-legal pattern)
    static cudaStream_t s_side = nullptr;
    static cudaEvent_t  ev_fork = nullptr, ev_join = nullptr;
    if (s_side == nullptr) {
        cudaStreamCreateWithFlags(&s_side, cudaStreamNonBlocking);
        cudaEventCreateWithFlags(&ev_fork, cudaEventDisableTiming);
        cudaEventCreateWithFlags(&ev_join, cudaEventDisableTiming);
    }

    // ---- fork: graph build on side stream, GEMMs on main stream ----
    cudaEventRecord(ev_fork, 0);
    cudaStreamWaitEvent(s_side, ev_fork, 0);

    k_init <<<(Nn + 255) / 256, 256, 0, s_side>>>(Nn);
    k_count<<<(E + 255) / 256, 256, 0, s_side>>>(ei, E);
    k_dinv <<<(Nn + 255) / 256, 256, 0, s_side>>>(Nn);

    // main stream: input projection + layer-0 transform GEMM (TRANSFORM=2: plain ReLU)
    k_gemm<0, 0><<<mblocks, 128>>>(x, W_in, P, Nn, nullptr, nullptr, b_in);
    k_gemm<2, 1><<<mblocks, 128>>>(P, Ws, HWp, Nn, nullptr, nullptr, nullptr);

    k_chunksum  <<<nb, 256, 0, s_side>>>(Nn);
    k_scanchunks<<<1, 32, 0, s_side>>>(nb);
    k_scanlocal <<<nb, 1024, 0, s_side>>>(Nn, E);
    k_scatter   <<<(E + 255) / 256, 256, 0, s_side>>>(ei, E);
    k_gstart    <<<(G + 256) / 256, 256, 0, s_side>>>(batch, Nn, G);

    // ---- join before first aggregation (needs CSR + dinv + zeroed BN sums) ----
    cudaEventRecord(ev_join, s_side);
    cudaStreamWaitEvent(0, ev_join, 0);

    int ablocks = (Nn * 32 + 255) / 256;
    for (int l = 0; l < LAYERS; l++) {
        if (l > 0)
            k_gemm<1, 1><<<mblocks, 128>>>(P, Ws + l * H * H, HWp, Nn,
                                           ts + l * H, tt + l * H, nullptr);
        k_agg<<<ablocks, 256>>>((const __half*)HWp, bs + l * H, P, Nn, l, gammas, betas);
    }

    k_poolmlp<<<G, 256>>>(P, W1, b1, W2, b2, (float*)d_out);
}

// round 14
// speedup vs baseline: 1.0912x; 1.0912x over previous
#include <cuda_runtime.h>
#include <cuda_fp16.h>
#include <cstdint>
#include <cstddef>

#define H      128
#define EMB    64
#define LAYERS 3
#define N_MAX  100000
#define E_MAX  1600000
#define G_MAX  1024

// ---------------- scratch (device globals; no allocation allowed) ----------------
__device__ float g_P [(size_t)N_MAX * H];   // pre-BN activations (fp32)
__device__ float g_HW[(size_t)N_MAX * H];   // layer GEMM output; stored as fp16 (reused buffer)
__device__ int   g_deg[N_MAX];
__device__ float g_dinv[N_MAX];
__device__ int   g_rowptr[N_MAX + 1];
__device__ int   g_cursor[N_MAX];
__device__ int   g_csrsrc[E_MAX];
__device__ float g_csrw[E_MAX];
__device__ int   g_chunksum[128];
__device__ int   g_chunkoff[128];
__device__ float g_bnsum[LAYERS * H];
__device__ float g_bnsq [LAYERS * H];
__device__ float g_ts[(LAYERS + 1) * H];
__device__ float g_tt[(LAYERS + 1) * H];
__device__ int   g_aggdone[LAYERS];         // last-block counters for fused bnfin
__device__ int   g_gstart[G_MAX + 1];

// ---------------- init ----------------
__global__ void k_init(int Nn) {
    int i = blockIdx.x * blockDim.x + threadIdx.x;
    if (i < Nn) { g_deg[i] = 0; g_cursor[i] = 0; }
    if (i < LAYERS * H) { g_bnsum[i] = 0.0f; g_bnsq[i] = 0.0f; }
    if (i < LAYERS) g_aggdone[i] = 0;
}

// ---------------- degree count / dinv ----------------
__global__ void k_count(const int* __restrict__ ei, int E) {
    int e = blockIdx.x * blockDim.x + threadIdx.x;
    if (e < E) atomicAdd(&g_deg[ei[E + e]], 1);
}

__global__ void k_dinv(int Nn) {
    int i = blockIdx.x * blockDim.x + threadIdx.x;
    if (i < Nn) g_dinv[i] = rsqrtf((float)g_deg[i] + 1.0f);
}

// ---------------- exclusive scan (1024-elem chunks) ----------------
__global__ void k_chunksum(int Nn) {
    __shared__ int sm[256];
    int base = blockIdx.x * 1024;
    int s = 0;
    for (int j = threadIdx.x; j < 1024; j += 256) {
        int i = base + j;
        if (i < Nn) s += g_deg[i];
    }
    sm[threadIdx.x] = s; __syncthreads();
    for (int d = 128; d > 0; d >>= 1) {
        if (threadIdx.x < d) sm[threadIdx.x] += sm[threadIdx.x + d];
        __syncthreads();
    }
    if (threadIdx.x == 0) g_chunksum[blockIdx.x] = sm[0];
}

__global__ void k_scanchunks(int nb) {
    if (threadIdx.x == 0) {
        int acc = 0;
        for (int b = 0; b < nb; b++) { g_chunkoff[b] = acc; acc += g_chunksum[b]; }
    }
}

__global__ void k_scanlocal(int Nn, int E) {
    __shared__ int sm[1024];
    int i = blockIdx.x * 1024 + threadIdx.x;
    int v = (i < Nn) ? g_deg[i] : 0;
    sm[threadIdx.x] = v; __syncthreads();
    for (int d = 1; d < 1024; d <<= 1) {
        int x = (threadIdx.x >= d) ? sm[threadIdx.x - d] : 0;
        __syncthreads();
        sm[threadIdx.x] += x;
        __syncthreads();
    }
    if (i < Nn) g_rowptr[i] = g_chunkoff[blockIdx.x] + sm[threadIdx.x] - v;  // exclusive
    if (i == 0) g_rowptr[Nn] = E;
}

// ---------------- CSR scatter ----------------
__global__ void k_scatter(const int* __restrict__ ei, int E) {
    int e = blockIdx.x * blockDim.x + threadIdx.x;
    if (e >= E) return;
    int s = ei[e], d = ei[E + e];
    int pos = g_rowptr[d] + atomicAdd(&g_cursor[d], 1);
    g_csrsrc[pos] = s;
    g_csrw[pos]   = g_dinv[s] * g_dinv[d];
}

// ---------------- graph boundary (batch is sorted) ----------------
__global__ void k_gstart(const int* __restrict__ batch, int Nn, int G) {
    int g = blockIdx.x * blockDim.x + threadIdx.x;
    if (g > G) return;
    if (g == G) { g_gstart[G] = Nn; return; }
    int lo = 0, hi = Nn;
    while (lo < hi) {
        int mid = (lo + hi) >> 1;
        if (batch[mid] < g) lo = mid + 1; else hi = mid;
    }
    g_gstart[g] = lo;
}

// ---------------- packed f32x2 helpers ----------------
__device__ __forceinline__ void fma_f32x2(unsigned long long& acc,
                                          unsigned long long a,
                                          unsigned long long b) {
    asm("fma.rn.f32x2 %0, %1, %2, %0;" : "+l"(acc) : "l"(a), "l"(b));
}
__device__ __forceinline__ unsigned long long dup_f32(float v) {
    unsigned long long r;
    asm("mov.b64 %0, {%1, %1};" : "=l"(r) : "f"(v));
    return r;
}

// ---------------- SGEMM (FFMA2, 16x8 tile, 128 thr, 2 CTAs/SM) — ROUND-12 FROZEN --
// Block tile M=128 x N=128, 128 threads.  Thread: 16 M-rows (8 packed pairs) x 8 N.
// Single-buffered smem, two barriers per k-tile (load-bearing for ptxas scheduling).
// TRANSFORM: 0 = identity (+bias), 1 = BN(s,t)+ReLU, 2 = plain ReLU
// OUTHALF=1: C stored as fp16 for the aggregation gather
#define MT 128
template <int TRANSFORM, int OUTHALF>
__global__ void __launch_bounds__(128, 2) k_gemm(
    const float* __restrict__ A, const float* __restrict__ B, void* __restrict__ C,
    int M, const float* __restrict__ s, const float* __restrict__ t,
    const float* __restrict__ bias)
{
    __shared__ float As[16][MT + 8];   // [k][m], m contiguous for 64-bit pair loads
    __shared__ float Bs[16][128];      // [k][n]
    const int tid = threadIdx.x;
    const int tx = tid & 15, ty = tid >> 4;
    const int m0 = blockIdx.x * MT;

    const int arow0 = tid >> 2, ac4 = (tid & 3) * 4;   // A: 4 pieces, rows arow0 + l*32
    const int brow0 = tid >> 5, bcc = (tid & 31) * 4;  // B: 4 pieces, rows brow0 + l*4

    float4 sv = make_float4(0.f, 0.f, 0.f, 0.f);
    float4 tv = make_float4(0.f, 0.f, 0.f, 0.f);

    unsigned long long acc2[8][8];
#pragma unroll
    for (int i = 0; i < 8; i++)
#pragma unroll
        for (int j = 0; j < 8; j++) acc2[i][j] = 0ULL;

    float4 pa[4], pb[4];

    // ---- load tile kt=0 into regs ----
#pragma unroll
    for (int l = 0; l < 4; l++) {
        int gm = m0 + arow0 + l * 32;
        pa[l] = (gm < M) ? *(const float4*)(A + (size_t)gm * H + ac4)
                         : make_float4(0.f, 0.f, 0.f, 0.f);
    }
#pragma unroll
    for (int l = 0; l < 4; l++)
        pb[l] = *(const float4*)(B + (size_t)(brow0 + l * 4) * H + bcc);

    // stage tile 0 to smem
    {
        if (TRANSFORM == 1) {
            sv = *(const float4*)(s + ac4);
            tv = *(const float4*)(t + ac4);
        }
#pragma unroll
        for (int l = 0; l < 4; l++) {
            float4 v = pa[l];
            if (TRANSFORM == 1) {
                v.x = fmaxf(fmaf(v.x, sv.x, tv.x), 0.f);
                v.y = fmaxf(fmaf(v.y, sv.y, tv.y), 0.f);
                v.z = fmaxf(fmaf(v.z, sv.z, tv.z), 0.f);
                v.w = fmaxf(fmaf(v.w, sv.w, tv.w), 0.f);
            } else if (TRANSFORM == 2) {
                v.x = fmaxf(v.x, 0.f); v.y = fmaxf(v.y, 0.f);
                v.z = fmaxf(v.z, 0.f); v.w = fmaxf(v.w, 0.f);
            }
            int row = arow0 + l * 32;
            As[ac4 + 0][row] = v.x; As[ac4 + 1][row] = v.y;
            As[ac4 + 2][row] = v.z; As[ac4 + 3][row] = v.w;
        }
#pragma unroll
        for (int l = 0; l < 4; l++)
            *(float4*)(&Bs[brow0 + l * 4][bcc]) = pb[l];
    }
    __syncthreads();

    for (int it = 0; it < 8; it++) {
        const int ktn = (it + 1) * 16;
        // ---- prefetch tile it+1 ----
        if (it < 7) {
#pragma unroll
            for (int l = 0; l < 4; l++) {
                int gm = m0 + arow0 + l * 32;
                pa[l] = (gm < M) ? *(const float4*)(A + (size_t)gm * H + ktn + ac4)
                                 : make_float4(0.f, 0.f, 0.f, 0.f);
            }
#pragma unroll
            for (int l = 0; l < 4; l++)
                pb[l] = *(const float4*)(B + (size_t)(ktn + brow0 + l * 4) * H + bcc);
        }
        // ---- compute tile it ----
#pragma unroll
        for (int k = 0; k < 16; k++) {
            unsigned long long a2[8];
            const float* Ak = &As[k][ty * 16];
            const ulonglong2 p0 = *(const ulonglong2*)(Ak);
            const ulonglong2 p1 = *(const ulonglong2*)(Ak + 4);
            const ulonglong2 p2 = *(const ulonglong2*)(Ak + 8);
            const ulonglong2 p3 = *(const ulonglong2*)(Ak + 12);
            a2[0] = p0.x; a2[1] = p0.y; a2[2] = p1.x; a2[3] = p1.y;
            a2[4] = p2.x; a2[5] = p2.y; a2[6] = p3.x; a2[7] = p3.y;
            float b[8];
            *(float4*)(b)     = *(const float4*)(&Bs[k][tx * 8]);
            *(float4*)(b + 4) = *(const float4*)(&Bs[k][tx * 8 + 4]);
            unsigned long long bd[8];
#pragma unroll
            for (int j = 0; j < 8; j++) bd[j] = dup_f32(b[j]);
#pragma unroll
            for (int i = 0; i < 8; i++)
#pragma unroll
                for (int j = 0; j < 8; j++)
                    fma_f32x2(acc2[i][j], a2[i], bd[j]);
        }
        __syncthreads();
        // ---- stage prefetched tile ----
        if (it < 7) {
            const int kg = ktn + ac4;
            if (TRANSFORM == 1) {
                sv = *(const float4*)(s + kg);
                tv = *(const float4*)(t + kg);
            }
#pragma unroll
            for (int l = 0; l < 4; l++) {
                float4 v = pa[l];
                if (TRANSFORM == 1) {
                    v.x = fmaxf(fmaf(v.x, sv.x, tv.x), 0.f);
                    v.y = fmaxf(fmaf(v.y, sv.y, tv.y), 0.f);
                    v.z = fmaxf(fmaf(v.z, sv.z, tv.z), 0.f);
                    v.w = fmaxf(fmaf(v.w, sv.w, tv.w), 0.f);
                } else if (TRANSFORM == 2) {
                    v.x = fmaxf(v.x, 0.f); v.y = fmaxf(v.y, 0.f);
                    v.z = fmaxf(v.z, 0.f); v.w = fmaxf(v.w, 0.f);
                }
                int row = arow0 + l * 32;
                As[ac4 + 0][row] = v.x; As[ac4 + 1][row] = v.y;
                As[ac4 + 2][row] = v.z; As[ac4 + 3][row] = v.w;
            }
#pragma unroll
            for (int l = 0; l < 4; l++)
                *(float4*)(&Bs[brow0 + l * 4][bcc]) = pb[l];
            __syncthreads();
        }
    }

    // epilogue: acc2[i2][j] = rows (ty*16 + 2*i2, +1), col tx*8+j
#pragma unroll
    for (int i2 = 0; i2 < 8; i2++) {
        int gm = m0 + ty * 16 + 2 * i2;
        float lo[8], hi[8];
#pragma unroll
        for (int j = 0; j < 8; j++) {
            float2 p = *(float2*)(&acc2[i2][j]);
            lo[j] = p.x; hi[j] = p.y;
        }
        if (bias) {
#pragma unroll
            for (int j = 0; j < 8; j++) {
                float bj = bias[tx * 8 + j];
                lo[j] += bj; hi[j] += bj;
            }
        }
        if (OUTHALF) {
            __half* Ch = (__half*)C;
            __half2 hv[4];
            if (gm < M) {
#pragma unroll
                for (int j2 = 0; j2 < 4; j2++)
                    hv[j2] = __floats2half2_rn(lo[2 * j2], lo[2 * j2 + 1]);
                *(uint4*)(Ch + (size_t)gm * H + tx * 8) = *(uint4*)hv;
            }
            if (gm + 1 < M) {
#pragma unroll
                for (int j2 = 0; j2 < 4; j2++)
                    hv[j2] = __floats2half2_rn(hi[2 * j2], hi[2 * j2 + 1]);
                *(uint4*)(Ch + (size_t)(gm + 1) * H + tx * 8) = *(uint4*)hv;
            }
        } else {
            float* Cf = (float*)C;
            if (gm < M) {
                *(float4*)(Cf + (size_t)gm * H + tx * 8)     = *(float4*)(lo);
                *(float4*)(Cf + (size_t)gm * H + tx * 8 + 4) = *(float4*)(lo + 4);
            }
            if (gm + 1 < M) {
                *(float4*)(Cf + (size_t)(gm + 1) * H + tx * 8)     = *(float4*)(hi);
                *(float4*)(Cf + (size_t)(gm + 1) * H + tx * 8 + 4) = *(float4*)(hi + 4);
            }
        }
    }
}

// ---------------- edge aggregation (2 nodes/warp, LDG.128) + fused BN -------------
// 16 lanes serve one node: each lane gathers 16B (8 halves) per edge.
// Per edge: 16 x LDG.128 instead of 32 x LDG.64; indices amortized per half-warp.
__global__ void __launch_bounds__(256) k_agg(
    const __half* __restrict__ HWh, const float* __restrict__ bias,
    float* __restrict__ OUT, int Nn, int layer,
    const float* __restrict__ gammas, const float* __restrict__ betas)
{
    __shared__ float s_sum[H], s_sq[H];
    const int tid  = threadIdx.x;
    const int l16  = tid & 15;            // lane within half-warp (channel group)
    if (tid < H) { s_sum[tid] = 0.f; s_sq[tid] = 0.f; }
    __syncthreads();

    int w = (blockIdx.x * blockDim.x + tid) >> 4;   // node = half-warp id
    if (w < Nn) {
        const uint4* hw4 = (const uint4*)HWh;       // 16B = 8 halves; 16 uint4 per row
        int e0 = g_rowptr[w], e1 = g_rowptr[w + 1];
        float acc[8];
#pragma unroll
        for (int j = 0; j < 8; j++) acc[j] = 0.f;

        int e = e0;
        for (; e + 4 <= e1; e += 4) {
            int   s0 = g_csrsrc[e],     s1 = g_csrsrc[e + 1];
            int   s2 = g_csrsrc[e + 2], s3 = g_csrsrc[e + 3];
            float w0 = g_csrw[e],       w1 = g_csrw[e + 1];
            float w2 = g_csrw[e + 2],   w3 = g_csrw[e + 3];
            uint4 u0 = hw4[(size_t)s0 * 16 + l16];
            uint4 u1 = hw4[(size_t)s1 * 16 + l16];
            uint4 u2 = hw4[(size_t)s2 * 16 + l16];
            uint4 u3 = hw4[(size_t)s3 * 16 + l16];
#pragma unroll
            for (int q = 0; q < 4; q++) {
                float2 f0 = __half22float2(((const __half2*)&u0)[q]);
                float2 f1 = __half22float2(((const __half2*)&u1)[q]);
                float2 f2 = __half22float2(((const __half2*)&u2)[q]);
                float2 f3 = __half22float2(((const __half2*)&u3)[q]);
                acc[2*q]   = fmaf(w0, f0.x, fmaf(w1, f1.x, fmaf(w2, f2.x, fmaf(w3, f3.x, acc[2*q]))));
                acc[2*q+1] = fmaf(w0, f0.y, fmaf(w1, f1.y, fmaf(w2, f2.y, fmaf(w3, f3.y, acc[2*q+1]))));
            }
        }
        for (; e < e1; e++) {
            int   src = g_csrsrc[e];
            float wt  = g_csrw[e];
            uint4 u = hw4[(size_t)src * 16 + l16];
#pragma unroll
            for (int q = 0; q < 4; q++) {
                float2 f = __half22float2(((const __half2*)&u)[q]);
                acc[2*q]   = fmaf(wt, f.x, acc[2*q]);
                acc[2*q+1] = fmaf(wt, f.y, acc[2*q+1]);
            }
        }
        float di = g_dinv[w];
        float sn = di * di;                         // 1/deg (self-loop norm)
        uint4 su = hw4[(size_t)w * 16 + l16];
        const int cb = l16 * 8;
#pragma unroll
        for (int q = 0; q < 4; q++) {
            float2 f = __half22float2(((const __half2*)&su)[q]);
            acc[2*q]   = fmaf(sn, f.x, acc[2*q])   + bias[cb + 2*q];
            acc[2*q+1] = fmaf(sn, f.y, acc[2*q+1]) + bias[cb + 2*q+1];
        }
        float4 o0 = make_float4(acc[0], acc[1], acc[2], acc[3]);
        float4 o1 = make_float4(acc[4], acc[5], acc[6], acc[7]);
        *(float4*)(OUT + (size_t)w * H + cb)     = o0;
        *(float4*)(OUT + (size_t)w * H + cb + 4) = o1;

        // BN partial stats (8 channels per lane; 2-way conflict between warp halves)
#pragma unroll
        for (int j = 0; j < 8; j++) {
            atomicAdd(&s_sum[cb + j], acc[j]);
            atomicAdd(&s_sq [cb + j], acc[j] * acc[j]);
        }
    }
    __syncthreads();
    if (tid < H) {
        atomicAdd(&g_bnsum[layer * H + tid], s_sum[tid]);
        atomicAdd(&g_bnsq [layer * H + tid], s_sq[tid]);
    }

    // ---- last-block BN finalize (no k_bnfin launch) ----
    __shared__ int s_last;
    __threadfence();
    __syncthreads();
    if (tid == 0) {
        int prev = atomicAdd(&g_aggdone[layer], 1);
        s_last = (prev == gridDim.x - 1);
    }
    __syncthreads();
    if (s_last && tid < H) {
        float invN = 1.0f / (float)Nn;
        float mean = g_bnsum[layer * H + tid] * invN;
        float var  = g_bnsq [layer * H + tid] * invN - mean * mean;
        float inv  = rsqrtf(var + 1e-5f);
        float sc   = gammas[layer * H + tid] * inv;
        g_ts[(layer + 1) * H + tid] = sc;
        g_tt[(layer + 1) * H + tid] = betas[layer * H + tid] - mean * sc;
    }
}

// ---------------- fused pool + head MLP (one block per graph) ----------------
__global__ void k_poolmlp(const float* __restrict__ P,
                          const float* __restrict__ W1, const float* __restrict__ b1,
                          const float* __restrict__ W2, const float* __restrict__ b2,
                          float* __restrict__ out) {
    __shared__ float p[H], t1[H];
    int g = blockIdx.x, c = threadIdx.x;
    int a = g_gstart[g], b = g_gstart[g + 1];
    float sc = g_ts[LAYERS * H + c], tt = g_tt[LAYERS * H + c];
    float acc = 0.f;
    for (int r = a; r < b; r++)
        acc += fmaxf(fmaf(P[(size_t)r * H + c], sc, tt), 0.f);
    p[c] = acc / fmaxf((float)(b - a), 1.0f);
    __syncthreads();

    float h1 = b1[c];
#pragma unroll
    for (int k = 0; k < H; k++) h1 = fmaf(p[k], W1[k * H + c], h1);
    t1[c] = fmaxf(h1, 0.f);
    __syncthreads();
    if (c < EMB) {
        float o = b2[c];
#pragma unroll
        for (int k = 0; k < H; k++) o = fmaf(t1[k], W2[k * EMB + c], o);
        out[(size_t)g * EMB + c] = o;
    }
}

// ---------------- launch ----------------
extern "C" void kernel_launch(void* const* d_in, const int* in_sizes, int n_in,
                              void* d_out, int out_size)
{
    const float* x      = (const float*)d_in[0];
    const int*   ei     = (const int*)  d_in[1];
    const int*   batch  = (const int*)  d_in[2];
    const float* W_in   = (const float*)d_in[3];
    const float* b_in   = (const float*)d_in[4];
    const float* Ws     = (const float*)d_in[5];
    const float* bs     = (const float*)d_in[6];
    const float* gammas = (const float*)d_in[7];
    const float* betas  = (const float*)d_in[8];
    const float* W1     = (const float*)d_in[9];
    const float* b1     = (const float*)d_in[10];
    const float* W2     = (const float*)d_in[11];
    const float* b2     = (const float*)d_in[12];

    int Nn = in_sizes[0] / H;
    int E  = in_sizes[1] / 2;
    int G  = out_size / EMB;

    float *P, *ts, *tt;
    void* HWp;
    cudaGetSymbolAddress((void**)&P,   g_P);
    cudaGetSymbolAddress(&HWp,         g_HW);
    cudaGetSymbolAddress((void**)&ts,  g_ts);
    cudaGetSymbolAddress((void**)&tt,  g_tt);

    int mblocks = (Nn + MT - 1) / MT;
    int nb = (Nn + 1023) / 1024;

    // side stream + fork/join events (created once; capture-legal pattern)
    static cudaStream_t s_side = nullptr;
    static cudaEvent_t  ev_fork = nullptr, ev_join = nullptr;
    if (s_side == nullptr) {
        cudaStreamCreateWithFlags(&s_side, cudaStreamNonBlocking);
        cudaEventCreateWithFlags(&ev_fork, cudaEventDisableTiming);
        cudaEventCreateWithFlags(&ev_join, cudaEventDisableTiming);
    }

    // ---- fork: graph build on side stream, GEMMs on main stream ----
    cudaEventRecord(ev_fork, 0);
    cudaStreamWaitEvent(s_side, ev_fork, 0);

    k_init <<<(Nn + 255) / 256, 256, 0, s_side>>>(Nn);
    k_count<<<(E + 255) / 256, 256, 0, s_side>>>(ei, E);
    k_dinv <<<(Nn + 255) / 256, 256, 0, s_side>>>(Nn);

    // main stream: input projection + layer-0 transform GEMM (TRANSFORM=2: plain ReLU)
    k_gemm<0, 0><<<mblocks, 128>>>(x, W_in, P, Nn, nullptr, nullptr, b_in);
    k_gemm<2, 1><<<mblocks, 128>>>(P, Ws, HWp, Nn, nullptr, nullptr, nullptr);

    k_chunksum  <<<nb, 256, 0, s_side>>>(Nn);
    k_scanchunks<<<1, 32, 0, s_side>>>(nb);
    k_scanlocal <<<nb, 1024, 0, s_side>>>(Nn, E);
    k_scatter   <<<(E + 255) / 256, 256, 0, s_side>>>(ei, E);
    k_gstart    <<<(G + 256) / 256, 256, 0, s_side>>>(batch, Nn, G);

    // ---- join before first aggregation (needs CSR + dinv + zeroed BN sums) ----
    cudaEventRecord(ev_join, s_side);
    cudaStreamWaitEvent(0, ev_join, 0);

    int ablocks = (Nn * 16 + 255) / 256;   // 16 threads per node now
    for (int l = 0; l < LAYERS; l++) {
        if (l > 0)
            k_gemm<1, 1><<<mblocks, 128>>>(P, Ws + l * H * H, HWp, Nn,
                                           ts + l * H, tt + l * H, nullptr);
        k_agg<<<ablocks, 256>>>((const __half*)HWp, bs + l * H, P, Nn, l, gammas, betas);
    }

    k_poolmlp<<<G, 128>>>(P, W1, b1, W2, b2, (float*)d_out);
}

// round 15
// speedup vs baseline: 1.2785x; 1.1717x over previous
#include <cuda_runtime.h>
#include <cuda_fp16.h>
#include <cstdint>
#include <cstddef>

#define H      128
#define EMB    64
#define LAYERS 3
#define N_MAX  100000
#define E_MAX  1600000
#define G_MAX  1024

// ---------------- scratch (device globals; no allocation allowed) ----------------
__device__ float g_P [(size_t)N_MAX * H];   // pre-BN activations (fp32)
__device__ float g_HW[(size_t)N_MAX * H];   // layer GEMM output; stored as fp16 (reused buffer)
__device__ int   g_deg[N_MAX];
__device__ float g_dinv[N_MAX];
__device__ int   g_rowptr[N_MAX + 1];
__device__ int   g_cursor[N_MAX];
__device__ int   g_csrsrc[E_MAX];
__device__ float g_csrw[E_MAX];
__device__ int   g_chunksum[128];
__device__ int   g_chunkoff[128];
__device__ float g_bnsum[LAYERS * H];
__device__ float g_bnsq [LAYERS * H];
__device__ float g_ts[(LAYERS + 1) * H];
__device__ float g_tt[(LAYERS + 1) * H];
__device__ int   g_aggdone[LAYERS];         // last-block counters for fused bnfin
__device__ int   g_gstart[G_MAX + 1];

// ---------------- init ----------------
__global__ void k_init(int Nn) {
    int i = blockIdx.x * blockDim.x + threadIdx.x;
    if (i < Nn) { g_deg[i] = 0; g_cursor[i] = 0; }
    if (i < LAYERS * H) { g_bnsum[i] = 0.0f; g_bnsq[i] = 0.0f; }
    if (i < LAYERS) g_aggdone[i] = 0;
}

// ---------------- degree count / dinv ----------------
__global__ void k_count(const int* __restrict__ ei, int E) {
    int e = blockIdx.x * blockDim.x + threadIdx.x;
    if (e < E) atomicAdd(&g_deg[__ldcs(ei + E + e)], 1);
}

__global__ void k_dinv(int Nn) {
    int i = blockIdx.x * blockDim.x + threadIdx.x;
    if (i < Nn) g_dinv[i] = rsqrtf((float)g_deg[i] + 1.0f);
}

// ---------------- exclusive scan (1024-elem chunks) ----------------
__global__ void k_chunksum(int Nn) {
    __shared__ int sm[256];
    int base = blockIdx.x * 1024;
    int s = 0;
    for (int j = threadIdx.x; j < 1024; j += 256) {
        int i = base + j;
        if (i < Nn) s += g_deg[i];
    }
    sm[threadIdx.x] = s; __syncthreads();
    for (int d = 128; d > 0; d >>= 1) {
        if (threadIdx.x < d) sm[threadIdx.x] += sm[threadIdx.x + d];
        __syncthreads();
    }
    if (threadIdx.x == 0) g_chunksum[blockIdx.x] = sm[0];
}

__global__ void k_scanchunks(int nb) {
    if (threadIdx.x == 0) {
        int acc = 0;
        for (int b = 0; b < nb; b++) { g_chunkoff[b] = acc; acc += g_chunksum[b]; }
    }
}

__global__ void k_scanlocal(int Nn, int E) {
    __shared__ int sm[1024];
    int i = blockIdx.x * 1024 + threadIdx.x;
    int v = (i < Nn) ? g_deg[i] : 0;
    sm[threadIdx.x] = v; __syncthreads();
    for (int d = 1; d < 1024; d <<= 1) {
        int x = (threadIdx.x >= d) ? sm[threadIdx.x - d] : 0;
        __syncthreads();
        sm[threadIdx.x] += x;
        __syncthreads();
    }
    if (i < Nn) g_rowptr[i] = g_chunkoff[blockIdx.x] + sm[threadIdx.x] - v;  // exclusive
    if (i == 0) g_rowptr[Nn] = E;
}

// ---------------- CSR scatter ----------------
__global__ void k_scatter(const int* __restrict__ ei, int E) {
    int e = blockIdx.x * blockDim.x + threadIdx.x;
    if (e >= E) return;
    int s = __ldcs(ei + e), d = __ldcs(ei + E + e);
    int pos = g_rowptr[d] + atomicAdd(&g_cursor[d], 1);
    g_csrsrc[pos] = s;
    g_csrw[pos]   = g_dinv[s] * g_dinv[d];
}

// ---------------- graph boundary (batch is sorted) ----------------
__global__ void k_gstart(const int* __restrict__ batch, int Nn, int G) {
    int g = blockIdx.x * blockDim.x + threadIdx.x;
    if (g > G) return;
    if (g == G) { g_gstart[G] = Nn; return; }
    int lo = 0, hi = Nn;
    while (lo < hi) {
        int mid = (lo + hi) >> 1;
        if (batch[mid] < g) lo = mid + 1; else hi = mid;
    }
    g_gstart[g] = lo;
}

// ---------------- packed f32x2 helpers ----------------
__device__ __forceinline__ void fma_f32x2(unsigned long long& acc,
                                          unsigned long long a,
                                          unsigned long long b) {
    asm("fma.rn.f32x2 %0, %1, %2, %0;" : "+l"(acc) : "l"(a), "l"(b));
}
__device__ __forceinline__ unsigned long long dup_f32(float v) {
    unsigned long long r;
    asm("mov.b64 %0, {%1, %1};" : "=l"(r) : "f"(v));
    return r;
}

// ---------------- SGEMM (FFMA2, 16x8 tile, 128 thr, 2 CTAs/SM) — ROUND-12 FROZEN --
// Block tile M=128 x N=128, 128 threads.  Thread: 16 M-rows (8 packed pairs) x 8 N.
// Single-buffered smem, two barriers per k-tile (load-bearing for ptxas scheduling).
// TRANSFORM: 0 = identity (+bias), 1 = BN(s,t)+ReLU, 2 = plain ReLU
// OUTHALF=1: C stored as fp16 for the aggregation gather
#define MT 128
template <int TRANSFORM, int OUTHALF>
__global__ void __launch_bounds__(128, 2) k_gemm(
    const float* __restrict__ A, const float* __restrict__ B, void* __restrict__ C,
    int M, const float* __restrict__ s, const float* __restrict__ t,
    const float* __restrict__ bias)
{
    __shared__ float As[16][MT + 8];   // [k][m], m contiguous for 64-bit pair loads
    __shared__ float Bs[16][128];      // [k][n]
    const int tid = threadIdx.x;
    const int tx = tid & 15, ty = tid >> 4;
    const int m0 = blockIdx.x * MT;

    const int arow0 = tid >> 2, ac4 = (tid & 3) * 4;   // A: 4 pieces, rows arow0 + l*32
    const int brow0 = tid >> 5, bcc = (tid & 31) * 4;  // B: 4 pieces, rows brow0 + l*4

    float4 sv = make_float4(0.f, 0.f, 0.f, 0.f);
    float4 tv = make_float4(0.f, 0.f, 0.f, 0.f);

    unsigned long long acc2[8][8];
#pragma unroll
    for (int i = 0; i < 8; i++)
#pragma unroll
        for (int j = 0; j < 8; j++) acc2[i][j] = 0ULL;

    float4 pa[4], pb[4];

    // ---- load tile kt=0 into regs ----
#pragma unroll
    for (int l = 0; l < 4; l++) {
        int gm = m0 + arow0 + l * 32;
        pa[l] = (gm < M) ? *(const float4*)(A + (size_t)gm * H + ac4)
                         : make_float4(0.f, 0.f, 0.f, 0.f);
    }
#pragma unroll
    for (int l = 0; l < 4; l++)
        pb[l] = *(const float4*)(B + (size_t)(brow0 + l * 4) * H + bcc);

    // stage tile 0 to smem
    {
        if (TRANSFORM == 1) {
            sv = *(const float4*)(s + ac4);
            tv = *(const float4*)(t + ac4);
        }
#pragma unroll
        for (int l = 0; l < 4; l++) {
            float4 v = pa[l];
            if (TRANSFORM == 1) {
                v.x = fmaxf(fmaf(v.x, sv.x, tv.x), 0.f);
                v.y = fmaxf(fmaf(v.y, sv.y, tv.y), 0.f);
                v.z = fmaxf(fmaf(v.z, sv.z, tv.z), 0.f);
                v.w = fmaxf(fmaf(v.w, sv.w, tv.w), 0.f);
            } else if (TRANSFORM == 2) {
                v.x = fmaxf(v.x, 0.f); v.y = fmaxf(v.y, 0.f);
                v.z = fmaxf(v.z, 0.f); v.w = fmaxf(v.w, 0.f);
            }
            int row = arow0 + l * 32;
            As[ac4 + 0][row] = v.x; As[ac4 + 1][row] = v.y;
            As[ac4 + 2][row] = v.z; As[ac4 + 3][row] = v.w;
        }
#pragma unroll
        for (int l = 0; l < 4; l++)
            *(float4*)(&Bs[brow0 + l * 4][bcc]) = pb[l];
    }
    __syncthreads();

    for (int it = 0; it < 8; it++) {
        const int ktn = (it + 1) * 16;
        // ---- prefetch tile it+1 ----
        if (it < 7) {
#pragma unroll
            for (int l = 0; l < 4; l++) {
                int gm = m0 + arow0 + l * 32;
                pa[l] = (gm < M) ? *(const float4*)(A + (size_t)gm * H + ktn + ac4)
                                 : make_float4(0.f, 0.f, 0.f, 0.f);
            }
#pragma unroll
            for (int l = 0; l < 4; l++)
                pb[l] = *(const float4*)(B + (size_t)(ktn + brow0 + l * 4) * H + bcc);
        }
        // ---- compute tile it ----
#pragma unroll
        for (int k = 0; k < 16; k++) {
            unsigned long long a2[8];
            const float* Ak = &As[k][ty * 16];
            const ulonglong2 p0 = *(const ulonglong2*)(Ak);
            const ulonglong2 p1 = *(const ulonglong2*)(Ak + 4);
            const ulonglong2 p2 = *(const ulonglong2*)(Ak + 8);
            const ulonglong2 p3 = *(const ulonglong2*)(Ak + 12);
            a2[0] = p0.x; a2[1] = p0.y; a2[2] = p1.x; a2[3] = p1.y;
            a2[4] = p2.x; a2[5] = p2.y; a2[6] = p3.x; a2[7] = p3.y;
            float b[8];
            *(float4*)(b)     = *(const float4*)(&Bs[k][tx * 8]);
            *(float4*)(b + 4) = *(const float4*)(&Bs[k][tx * 8 + 4]);
            unsigned long long bd[8];
#pragma unroll
            for (int j = 0; j < 8; j++) bd[j] = dup_f32(b[j]);
#pragma unroll
            for (int i = 0; i < 8; i++)
#pragma unroll
                for (int j = 0; j < 8; j++)
                    fma_f32x2(acc2[i][j], a2[i], bd[j]);
        }
        __syncthreads();
        // ---- stage prefetched tile ----
        if (it < 7) {
            const int kg = ktn + ac4;
            if (TRANSFORM == 1) {
                sv = *(const float4*)(s + kg);
                tv = *(const float4*)(t + kg);
            }
#pragma unroll
            for (int l = 0; l < 4; l++) {
                float4 v = pa[l];
                if (TRANSFORM == 1) {
                    v.x = fmaxf(fmaf(v.x, sv.x, tv.x), 0.f);
                    v.y = fmaxf(fmaf(v.y, sv.y, tv.y), 0.f);
                    v.z = fmaxf(fmaf(v.z, sv.z, tv.z), 0.f);
                    v.w = fmaxf(fmaf(v.w, sv.w, tv.w), 0.f);
                } else if (TRANSFORM == 2) {
                    v.x = fmaxf(v.x, 0.f); v.y = fmaxf(v.y, 0.f);
                    v.z = fmaxf(v.z, 0.f); v.w = fmaxf(v.w, 0.f);
                }
                int row = arow0 + l * 32;
                As[ac4 + 0][row] = v.x; As[ac4 + 1][row] = v.y;
                As[ac4 + 2][row] = v.z; As[ac4 + 3][row] = v.w;
            }
#pragma unroll
            for (int l = 0; l < 4; l++)
                *(float4*)(&Bs[brow0 + l * 4][bcc]) = pb[l];
            __syncthreads();
        }
    }

    // epilogue: acc2[i2][j] = rows (ty*16 + 2*i2, +1), col tx*8+j
#pragma unroll
    for (int i2 = 0; i2 < 8; i2++) {
        int gm = m0 + ty * 16 + 2 * i2;
        float lo[8], hi[8];
#pragma unroll
        for (int j = 0; j < 8; j++) {
            float2 p = *(float2*)(&acc2[i2][j]);
            lo[j] = p.x; hi[j] = p.y;
        }
        if (bias) {
#pragma unroll
            for (int j = 0; j < 8; j++) {
                float bj = bias[tx * 8 + j];
                lo[j] += bj; hi[j] += bj;
            }
        }
        if (OUTHALF) {
            __half* Ch = (__half*)C;
            __half2 hv[4];
            if (gm < M) {
#pragma unroll
                for (int j2 = 0; j2 < 4; j2++)
                    hv[j2] = __floats2half2_rn(lo[2 * j2], lo[2 * j2 + 1]);
                *(uint4*)(Ch + (size_t)gm * H + tx * 8) = *(uint4*)hv;
            }
            if (gm + 1 < M) {
#pragma unroll
                for (int j2 = 0; j2 < 4; j2++)
                    hv[j2] = __floats2half2_rn(hi[2 * j2], hi[2 * j2 + 1]);
                *(uint4*)(Ch + (size_t)(gm + 1) * H + tx * 8) = *(uint4*)hv;
            }
        } else {
            float* Cf = (float*)C;
            if (gm < M) {
                *(float4*)(Cf + (size_t)gm * H + tx * 8)     = *(float4*)(lo);
                *(float4*)(Cf + (size_t)gm * H + tx * 8 + 4) = *(float4*)(lo + 4);
            }
            if (gm + 1 < M) {
                *(float4*)(Cf + (size_t)(gm + 1) * H + tx * 8)     = *(float4*)(hi);
                *(float4*)(Cf + (size_t)(gm + 1) * H + tx * 8 + 4) = *(float4*)(hi + 4);
            }
        }
    }
}

// ---------------- edge aggregation (warp/node, uint2) + fused BN — ROUND-12 -------
// warp per dst node; fp16 gather (x4 unrolled, MLP>=4), fp32 accumulate.
// CSR index/weight streams read with __ldcs (single-use, evict-first).
// Last block (atomic counter) computes ts/tt for the next layer.
__global__ void __launch_bounds__(256) k_agg(
    const __half* __restrict__ HWh, const float* __restrict__ bias,
    float* __restrict__ OUT, int Nn, int layer,
    const float* __restrict__ gammas, const float* __restrict__ betas)
{
    __shared__ float s_sum[H], s_sq[H];
    const int tid  = threadIdx.x;
    const int lane = tid & 31;
    if (tid < H) { s_sum[tid] = 0.f; s_sq[tid] = 0.f; }
    __syncthreads();

    int w = (blockIdx.x * blockDim.x + tid) >> 5;
    if (w < Nn) {
        const uint2* hw2 = (const uint2*)HWh;      // 8B = 4 halves per lane
        int e0 = g_rowptr[w], e1 = g_rowptr[w + 1];
        float4 acc = make_float4(0.f, 0.f, 0.f, 0.f);
        int e = e0;
        for (; e + 4 <= e1; e += 4) {
            int   s0 = __ldcs(g_csrsrc + e),     s1 = __ldcs(g_csrsrc + e + 1);
            int   s2 = __ldcs(g_csrsrc + e + 2), s3 = __ldcs(g_csrsrc + e + 3);
            float w0 = __ldcs(g_csrw + e),       w1 = __ldcs(g_csrw + e + 1);
            float w2 = __ldcs(g_csrw + e + 2),   w3 = __ldcs(g_csrw + e + 3);
            uint2 u0 = hw2[(size_t)s0 * 32 + lane];
            uint2 u1 = hw2[(size_t)s1 * 32 + lane];
            uint2 u2 = hw2[(size_t)s2 * 32 + lane];
            uint2 u3 = hw2[(size_t)s3 * 32 + lane];
            float2 a0 = __half22float2(*(__half2*)&u0.x), b0 = __half22float2(*(__half2*)&u0.y);
            float2 a1 = __half22float2(*(__half2*)&u1.x), b1 = __half22float2(*(__half2*)&u1.y);
            float2 a2 = __half22float2(*(__half2*)&u2.x), b2 = __half22float2(*(__half2*)&u2.y);
            float2 a3 = __half22float2(*(__half2*)&u3.x), b3 = __half22float2(*(__half2*)&u3.y);
            acc.x = fmaf(w0, a0.x, fmaf(w1, a1.x, fmaf(w2, a2.x, fmaf(w3, a3.x, acc.x))));
            acc.y = fmaf(w0, a0.y, fmaf(w1, a1.y, fmaf(w2, a2.y, fmaf(w3, a3.y, acc.y))));
            acc.z = fmaf(w0, b0.x, fmaf(w1, b1.x, fmaf(w2, b2.x, fmaf(w3, b3.x, acc.z))));
            acc.w = fmaf(w0, b0.y, fmaf(w1, b1.y, fmaf(w2, b2.y, fmaf(w3, b3.y, acc.w))));
        }
        for (; e < e1; e++) {
            int   src = __ldcs(g_csrsrc + e);
            float wt  = __ldcs(g_csrw + e);
            uint2 u = hw2[(size_t)src * 32 + lane];
            float2 f0 = __half22float2(*(__half2*)&u.x);
            float2 f1 = __half22float2(*(__half2*)&u.y);
            acc.x = fmaf(wt, f0.x, acc.x);
            acc.y = fmaf(wt, f0.y, acc.y);
            acc.z = fmaf(wt, f1.x, acc.z);
            acc.w = fmaf(wt, f1.y, acc.w);
        }
        float di = g_dinv[w];
        float sn = di * di;                       // 1/deg (self-loop norm)
        uint2 su = hw2[(size_t)w * 32 + lane];
        float2 s0 = __half22float2(*(__half2*)&su.x);
        float2 s1 = __half22float2(*(__half2*)&su.y);
        acc.x = fmaf(sn, s0.x, acc.x) + bias[lane * 4 + 0];
        acc.y = fmaf(sn, s0.y, acc.y) + bias[lane * 4 + 1];
        acc.z = fmaf(sn, s1.x, acc.z) + bias[lane * 4 + 2];
        acc.w = fmaf(sn, s1.y, acc.w) + bias[lane * 4 + 3];
        ((float4*)OUT)[(size_t)w * 32 + lane] = acc;

        atomicAdd(&s_sum[lane * 4 + 0], acc.x);
        atomicAdd(&s_sum[lane * 4 + 1], acc.y);
        atomicAdd(&s_sum[lane * 4 + 2], acc.z);
        atomicAdd(&s_sum[lane * 4 + 3], acc.w);
        atomicAdd(&s_sq[lane * 4 + 0], acc.x * acc.x);
        atomicAdd(&s_sq[lane * 4 + 1], acc.y * acc.y);
        atomicAdd(&s_sq[lane * 4 + 2], acc.z * acc.z);
        atomicAdd(&s_sq[lane * 4 + 3], acc.w * acc.w);
    }
    __syncthreads();
    if (tid < H) {
        atomicAdd(&g_bnsum[layer * H + tid], s_sum[tid]);
        atomicAdd(&g_bnsq [layer * H + tid], s_sq[tid]);
    }

    // ---- last-block BN finalize (replaces k_bnfin launch) ----
    __shared__ int s_last;
    __threadfence();
    __syncthreads();
    if (tid == 0) {
        int prev = atomicAdd(&g_aggdone[layer], 1);
        s_last = (prev == gridDim.x - 1);
    }
    __syncthreads();
    if (s_last && tid < H) {
        float invN = 1.0f / (float)Nn;
        float mean = g_bnsum[layer * H + tid] * invN;
        float var  = g_bnsq [layer * H + tid] * invN - mean * mean;
        float inv  = rsqrtf(var + 1e-5f);
        float sc   = gammas[layer * H + tid] * inv;
        g_ts[(layer + 1) * H + tid] = sc;
        g_tt[(layer + 1) * H + tid] = betas[layer * H + tid] - mean * sc;
    }
}

// ---------------- fused pool + head MLP (256 thr: 2 row-groups per graph) ---------
__global__ void k_poolmlp(const float* __restrict__ P,
                          const float* __restrict__ W1, const float* __restrict__ b1,
                          const float* __restrict__ W2, const float* __restrict__ b2,
                          float* __restrict__ out) {
    __shared__ float p[H], t1[H], part[H];
    int g = blockIdx.x;
    int c = threadIdx.x & 127;
    int grp = threadIdx.x >> 7;                 // 0 or 1
    int a = g_gstart[g], b = g_gstart[g + 1];
    float sc = g_ts[LAYERS * H + c], tt = g_tt[LAYERS * H + c];
    float acc = 0.f;
    for (int r = a + grp; r < b; r += 2)
        acc += fmaxf(fmaf(P[(size_t)r * H + c], sc, tt), 0.f);
    if (grp == 1) part[c] = acc;
    __syncthreads();
    if (grp == 0) p[c] = (acc + part[c]) / fmaxf((float)(b - a), 1.0f);
    __syncthreads();

    if (grp == 0) {
        float h1 = b1[c];
#pragma unroll
        for (int k = 0; k < H; k++) h1 = fmaf(p[k], W1[k * H + c], h1);
        t1[c] = fmaxf(h1, 0.f);
    }
    __syncthreads();
    if (grp == 0 && c < EMB) {
        float o = b2[c];
#pragma unroll
        for (int k = 0; k < H; k++) o = fmaf(t1[k], W2[k * EMB + c], o);
        out[(size_t)g * EMB + c] = o;
    }
}

// ---------------- launch ----------------
extern "C" void kernel_launch(void* const* d_in, const int* in_sizes, int n_in,
                              void* d_out, int out_size)
{
    const float* x      = (const float*)d_in[0];
    const int*   ei     = (const int*)  d_in[1];
    const int*   batch  = (const int*)  d_in[2];
    const float* W_in   = (const float*)d_in[3];
    const float* b_in   = (const float*)d_in[4];
    const float* Ws     = (const float*)d_in[5];
    const float* bs     = (const float*)d_in[6];
    const float* gammas = (const float*)d_in[7];
    const float* betas  = (const float*)d_in[8];
    const float* W1     = (const float*)d_in[9];
    const float* b1     = (const float*)d_in[10];
    const float* W2     = (const float*)d_in[11];
    const float* b2     = (const float*)d_in[12];

    int Nn = in_sizes[0] / H;
    int E  = in_sizes[1] / 2;
    int G  = out_size / EMB;

    float *P, *ts, *tt;
    void* HWp;
    cudaGetSymbolAddress((void**)&P,   g_P);
    cudaGetSymbolAddress(&HWp,         g_HW);
    cudaGetSymbolAddress((void**)&ts,  g_ts);
    cudaGetSymbolAddress((void**)&tt,  g_tt);

    int mblocks = (Nn + MT - 1) / MT;
    int nb = (Nn + 1023) / 1024;

    // side stream + fork/join events (created once; capture-legal pattern)
    static cudaStream_t s_side = nullptr;
    static cudaEvent_t  ev_fork = nullptr, ev_join = nullptr;
    if (s_side == nullptr) {
        cudaStreamCreateWithFlags(&s_side, cudaStreamNonBlocking);
        cudaEventCreateWithFlags(&ev_fork, cudaEventDisableTiming);
        cudaEventCreateWithFlags(&ev_join, cudaEventDisableTiming);
    }

    // ---- fork: graph build on side stream, GEMMs on main stream ----
    cudaEventRecord(ev_fork, 0);
    cudaStreamWaitEvent(s_side, ev_fork, 0);

    k_init <<<(Nn + 255) / 256, 256, 0, s_side>>>(Nn);
    k_count<<<(E + 255) / 256, 256, 0, s_side>>>(ei, E);
    k_dinv <<<(Nn + 255) / 256, 256, 0, s_side>>>(Nn);

    // main stream: input projection + layer-0 transform GEMM (TRANSFORM=2: plain ReLU)
    k_gemm<0, 0><<<mblocks, 128>>>(x, W_in, P, Nn, nullptr, nullptr, b_in);
    k_gemm<2, 1><<<mblocks, 128>>>(P, Ws, HWp, Nn, nullptr, nullptr, nullptr);

    k_chunksum  <<<nb, 256, 0, s_side>>>(Nn);
    k_scanchunks<<<1, 32, 0, s_side>>>(nb);
    k_scanlocal <<<nb, 1024, 0, s_side>>>(Nn, E);
    k_scatter   <<<(E + 255) / 256, 256, 0, s_side>>>(ei, E);
    k_gstart    <<<(G + 256) / 256, 256, 0, s_side>>>(batch, Nn, G);

    // ---- join before first aggregation (needs CSR + dinv + zeroed BN sums) ----
    cudaEventRecord(ev_join, s_side);
    cudaStreamWaitEvent(0, ev_join, 0);

    int ablocks = (Nn * 32 + 255) / 256;
    for (int l = 0; l < LAYERS; l++) {
        if (l > 0)
            k_gemm<1, 1><<<mblocks, 128>>>(P, Ws + l * H * H, HWp, Nn,
                                           ts + l * H, tt + l * H, nullptr);
        k_agg<<<ablocks, 256>>>((const __half*)HWp, bs + l * H, P, Nn, l, gammas, betas);
    }

    k_poolmlp<<<G, 256>>>(P, W1, b1, W2, b2, (float*)d_out);
}

// round 16
// speedup vs baseline: 1.2808x; 1.0017x over previous
#include <cuda_runtime.h>
#include <cuda_fp16.h>
#include <cstdint>
#include <cstddef>

#define H      128
#define EMB    64
#define LAYERS 3
#define N_MAX  100000
#define E_MAX  1600000
#define G_MAX  1024

// ---------------- scratch (device globals; no allocation allowed) ----------------
__device__ float g_P [(size_t)N_MAX * H];   // pre-BN activations (fp32)
__device__ float g_HW[(size_t)N_MAX * H];   // layer GEMM output; stored as fp16 (reused buffer)
__device__ int   g_deg[N_MAX];
__device__ float g_dinv[N_MAX];
__device__ int   g_rowptr[N_MAX + 1];
__device__ int   g_cursor[N_MAX];
__device__ int   g_csrsrc[E_MAX];
__device__ float g_csrw[E_MAX];
__device__ int   g_chunksum[128];
__device__ int   g_chunkoff[128];
__device__ float g_bnsum[LAYERS * H];
__device__ float g_bnsq [LAYERS * H];
__device__ float g_ts[(LAYERS + 1) * H];
__device__ float g_tt[(LAYERS + 1) * H];
__device__ int   g_aggdone[LAYERS];         // last-block counters for fused bnfin
__device__ int   g_gstart[G_MAX + 1];

// ---------------- init ----------------
__global__ void k_init(int Nn) {
    int i = blockIdx.x * blockDim.x + threadIdx.x;
    if (i < Nn) { g_deg[i] = 0; g_cursor[i] = 0; }
    if (i < LAYERS * H) { g_bnsum[i] = 0.0f; g_bnsq[i] = 0.0f; }
    if (i < LAYERS) g_aggdone[i] = 0;
}

// ---------------- degree count / dinv ----------------
__global__ void k_count(const int* __restrict__ ei, int E) {
    int e = blockIdx.x * blockDim.x + threadIdx.x;
    if (e < E) atomicAdd(&g_deg[__ldcs(ei + E + e)], 1);
}

__global__ void k_dinv(int Nn) {
    int i = blockIdx.x * blockDim.x + threadIdx.x;
    if (i < Nn) g_dinv[i] = rsqrtf((float)g_deg[i] + 1.0f);
}

// ---------------- exclusive scan (1024-elem chunks) ----------------
__global__ void k_chunksum(int Nn) {
    __shared__ int sm[256];
    int base = blockIdx.x * 1024;
    int s = 0;
    for (int j = threadIdx.x; j < 1024; j += 256) {
        int i = base + j;
        if (i < Nn) s += g_deg[i];
    }
    sm[threadIdx.x] = s; __syncthreads();
    for (int d = 128; d > 0; d >>= 1) {
        if (threadIdx.x < d) sm[threadIdx.x] += sm[threadIdx.x + d];
        __syncthreads();
    }
    if (threadIdx.x == 0) g_chunksum[blockIdx.x] = sm[0];
}

__global__ void k_scanchunks(int nb) {
    if (threadIdx.x == 0) {
        int acc = 0;
        for (int b = 0; b < nb; b++) { g_chunkoff[b] = acc; acc += g_chunksum[b]; }
    }
}

__global__ void k_scanlocal(int Nn, int E) {
    __shared__ int sm[1024];
    int i = blockIdx.x * 1024 + threadIdx.x;
    int v = (i < Nn) ? g_deg[i] : 0;
    sm[threadIdx.x] = v; __syncthreads();
    for (int d = 1; d < 1024; d <<= 1) {
        int x = (threadIdx.x >= d) ? sm[threadIdx.x - d] : 0;
        __syncthreads();
        sm[threadIdx.x] += x;
        __syncthreads();
    }
    if (i < Nn) g_rowptr[i] = g_chunkoff[blockIdx.x] + sm[threadIdx.x] - v;  // exclusive
    if (i == 0) g_rowptr[Nn] = E;
}

// ---------------- CSR scatter ----------------
__global__ void k_scatter(const int* __restrict__ ei, int E) {
    int e = blockIdx.x * blockDim.x + threadIdx.x;
    if (e >= E) return;
    int s = __ldcs(ei + e), d = __ldcs(ei + E + e);
    int pos = g_rowptr[d] + atomicAdd(&g_cursor[d], 1);
    g_csrsrc[pos] = s;
    g_csrw[pos]   = g_dinv[s] * g_dinv[d];
}

// ---------------- graph boundary (batch is sorted) ----------------
__global__ void k_gstart(const int* __restrict__ batch, int Nn, int G) {
    int g = blockIdx.x * blockDim.x + threadIdx.x;
    if (g > G) return;
    if (g == G) { g_gstart[G] = Nn; return; }
    int lo = 0, hi = Nn;
    while (lo < hi) {
        int mid = (lo + hi) >> 1;
        if (batch[mid] < g) lo = mid + 1; else hi = mid;
    }
    g_gstart[g] = lo;
}

// ---------------- packed f32x2 helpers ----------------
__device__ __forceinline__ void fma_f32x2(unsigned long long& acc,
                                          unsigned long long a,
                                          unsigned long long b) {
    asm("fma.rn.f32x2 %0, %1, %2, %0;" : "+l"(acc) : "l"(a), "l"(b));
}
__device__ __forceinline__ unsigned long long dup_f32(float v) {
    unsigned long long r;
    asm("mov.b64 %0, {%1, %1};" : "=l"(r) : "f"(v));
    return r;
}

// ---------------- SGEMM (FFMA2, 16x8 tile, 128 thr, 2 CTAs/SM) — ROUND-12 FROZEN --
// Block tile M=128 x N=128, 128 threads.  Thread: 16 M-rows (8 packed pairs) x 8 N.
// Single-buffered smem, two barriers per k-tile (load-bearing for ptxas scheduling).
// TRANSFORM: 0 = identity (+bias), 1 = BN(s,t)+ReLU, 2 = plain ReLU
// OUTHALF=1: C stored as fp16 for the aggregation gather
#define MT 128
template <int TRANSFORM, int OUTHALF>
__global__ void __launch_bounds__(128, 2) k_gemm(
    const float* __restrict__ A, const float* __restrict__ B, void* __restrict__ C,
    int M, const float* __restrict__ s, const float* __restrict__ t,
    const float* __restrict__ bias)
{
    __shared__ float As[16][MT + 8];   // [k][m], m contiguous for 64-bit pair loads
    __shared__ float Bs[16][128];      // [k][n]
    const int tid = threadIdx.x;
    const int tx = tid & 15, ty = tid >> 4;
    const int m0 = blockIdx.x * MT;

    const int arow0 = tid >> 2, ac4 = (tid & 3) * 4;   // A: 4 pieces, rows arow0 + l*32
    const int brow0 = tid >> 5, bcc = (tid & 31) * 4;  // B: 4 pieces, rows brow0 + l*4

    float4 sv = make_float4(0.f, 0.f, 0.f, 0.f);
    float4 tv = make_float4(0.f, 0.f, 0.f, 0.f);

    unsigned long long acc2[8][8];
#pragma unroll
    for (int i = 0; i < 8; i++)
#pragma unroll
        for (int j = 0; j < 8; j++) acc2[i][j] = 0ULL;

    float4 pa[4], pb[4];

    // ---- load tile kt=0 into regs ----
#pragma unroll
    for (int l = 0; l < 4; l++) {
        int gm = m0 + arow0 + l * 32;
        pa[l] = (gm < M) ? *(const float4*)(A + (size_t)gm * H + ac4)
                         : make_float4(0.f, 0.f, 0.f, 0.f);
    }
#pragma unroll
    for (int l = 0; l < 4; l++)
        pb[l] = *(const float4*)(B + (size_t)(brow0 + l * 4) * H + bcc);

    // stage tile 0 to smem
    {
        if (TRANSFORM == 1) {
            sv = *(const float4*)(s + ac4);
            tv = *(const float4*)(t + ac4);
        }
#pragma unroll
        for (int l = 0; l < 4; l++) {
            float4 v = pa[l];
            if (TRANSFORM == 1) {
                v.x = fmaxf(fmaf(v.x, sv.x, tv.x), 0.f);
                v.y = fmaxf(fmaf(v.y, sv.y, tv.y), 0.f);
                v.z = fmaxf(fmaf(v.z, sv.z, tv.z), 0.f);
                v.w = fmaxf(fmaf(v.w, sv.w, tv.w), 0.f);
            } else if (TRANSFORM == 2) {
                v.x = fmaxf(v.x, 0.f); v.y = fmaxf(v.y, 0.f);
                v.z = fmaxf(v.z, 0.f); v.w = fmaxf(v.w, 0.f);
            }
            int row = arow0 + l * 32;
            As[ac4 + 0][row] = v.x; As[ac4 + 1][row] = v.y;
            As[ac4 + 2][row] = v.z; As[ac4 + 3][row] = v.w;
        }
#pragma unroll
        for (int l = 0; l < 4; l++)
            *(float4*)(&Bs[brow0 + l * 4][bcc]) = pb[l];
    }
    __syncthreads();

    for (int it = 0; it < 8; it++) {
        const int ktn = (it + 1) * 16;
        // ---- prefetch tile it+1 ----
        if (it < 7) {
#pragma unroll
            for (int l = 0; l < 4; l++) {
                int gm = m0 + arow0 + l * 32;
                pa[l] = (gm < M) ? *(const float4*)(A + (size_t)gm * H + ktn + ac4)
                                 : make_float4(0.f, 0.f, 0.f, 0.f);
            }
#pragma unroll
            for (int l = 0; l < 4; l++)
                pb[l] = *(const float4*)(B + (size_t)(ktn + brow0 + l * 4) * H + bcc);
        }
        // ---- compute tile it ----
#pragma unroll
        for (int k = 0; k < 16; k++) {
            unsigned long long a2[8];
            const float* Ak = &As[k][ty * 16];
            const ulonglong2 p0 = *(const ulonglong2*)(Ak);
            const ulonglong2 p1 = *(const ulonglong2*)(Ak + 4);
            const ulonglong2 p2 = *(const ulonglong2*)(Ak + 8);
            const ulonglong2 p3 = *(const ulonglong2*)(Ak + 12);
            a2[0] = p0.x; a2[1] = p0.y; a2[2] = p1.x; a2[3] = p1.y;
            a2[4] = p2.x; a2[5] = p2.y; a2[6] = p3.x; a2[7] = p3.y;
            float b[8];
            *(float4*)(b)     = *(const float4*)(&Bs[k][tx * 8]);
            *(float4*)(b + 4) = *(const float4*)(&Bs[k][tx * 8 + 4]);
            unsigned long long bd[8];
#pragma unroll
            for (int j = 0; j < 8; j++) bd[j] = dup_f32(b[j]);
#pragma unroll
            for (int i = 0; i < 8; i++)
#pragma unroll
                for (int j = 0; j < 8; j++)
                    fma_f32x2(acc2[i][j], a2[i], bd[j]);
        }
        __syncthreads();
        // ---- stage prefetched tile ----
        if (it < 7) {
            const int kg = ktn + ac4;
            if (TRANSFORM == 1) {
                sv = *(const float4*)(s + kg);
                tv = *(const float4*)(t + kg);
            }
#pragma unroll
            for (int l = 0; l < 4; l++) {
                float4 v = pa[l];
                if (TRANSFORM == 1) {
                    v.x = fmaxf(fmaf(v.x, sv.x, tv.x), 0.f);
                    v.y = fmaxf(fmaf(v.y, sv.y, tv.y), 0.f);
                    v.z = fmaxf(fmaf(v.z, sv.z, tv.z), 0.f);
                    v.w = fmaxf(fmaf(v.w, sv.w, tv.w), 0.f);
                } else if (TRANSFORM == 2) {
                    v.x = fmaxf(v.x, 0.f); v.y = fmaxf(v.y, 0.f);
                    v.z = fmaxf(v.z, 0.f); v.w = fmaxf(v.w, 0.f);
                }
                int row = arow0 + l * 32;
                As[ac4 + 0][row] = v.x; As[ac4 + 1][row] = v.y;
                As[ac4 + 2][row] = v.z; As[ac4 + 3][row] = v.w;
            }
#pragma unroll
            for (int l = 0; l < 4; l++)
                *(float4*)(&Bs[brow0 + l * 4][bcc]) = pb[l];
            __syncthreads();
        }
    }

    // epilogue: acc2[i2][j] = rows (ty*16 + 2*i2, +1), col tx*8+j
#pragma unroll
    for (int i2 = 0; i2 < 8; i2++) {
        int gm = m0 + ty * 16 + 2 * i2;
        float lo[8], hi[8];
#pragma unroll
        for (int j = 0; j < 8; j++) {
            float2 p = *(float2*)(&acc2[i2][j]);
            lo[j] = p.x; hi[j] = p.y;
        }
        if (bias) {
#pragma unroll
            for (int j = 0; j < 8; j++) {
                float bj = bias[tx * 8 + j];
                lo[j] += bj; hi[j] += bj;
            }
        }
        if (OUTHALF) {
            __half* Ch = (__half*)C;
            __half2 hv[4];
            if (gm < M) {
#pragma unroll
                for (int j2 = 0; j2 < 4; j2++)
                    hv[j2] = __floats2half2_rn(lo[2 * j2], lo[2 * j2 + 1]);
                *(uint4*)(Ch + (size_t)gm * H + tx * 8) = *(uint4*)hv;
            }
            if (gm + 1 < M) {
#pragma unroll
                for (int j2 = 0; j2 < 4; j2++)
                    hv[j2] = __floats2half2_rn(hi[2 * j2], hi[2 * j2 + 1]);
                *(uint4*)(Ch + (size_t)(gm + 1) * H + tx * 8) = *(uint4*)hv;
            }
        } else {
            float* Cf = (float*)C;
            if (gm < M) {
                *(float4*)(Cf + (size_t)gm * H + tx * 8)     = *(float4*)(lo);
                *(float4*)(Cf + (size_t)gm * H + tx * 8 + 4) = *(float4*)(lo + 4);
            }
            if (gm + 1 < M) {
                *(float4*)(Cf + (size_t)(gm + 1) * H + tx * 8)     = *(float4*)(hi);
                *(float4*)(Cf + (size_t)(gm + 1) * H + tx * 8 + 4) = *(float4*)(hi + 4);
            }
        }
    }
}

// ---------------- edge aggregation (warp/node, x8-unrolled gather) + fused BN -----
// warp per dst node; fp16 gather with 8 loads in flight (latency-bound -> MLP=8),
// fp32 accumulate.  Last block computes ts/tt for the next layer (no bnfin launch).
__global__ void __launch_bounds__(256) k_agg(
    const __half* __restrict__ HWh, const float* __restrict__ bias,
    float* __restrict__ OUT, int Nn, int layer,
    const float* __restrict__ gammas, const float* __restrict__ betas)
{
    __shared__ float s_sum[H], s_sq[H];
    const int tid  = threadIdx.x;
    const int lane = tid & 31;
    if (tid < H) { s_sum[tid] = 0.f; s_sq[tid] = 0.f; }
    __syncthreads();

    int w = (blockIdx.x * blockDim.x + tid) >> 5;
    if (w < Nn) {
        const uint2* hw2 = (const uint2*)HWh;      // 8B = 4 halves per lane
        int e0 = g_rowptr[w], e1 = g_rowptr[w + 1];
        float4 acc = make_float4(0.f, 0.f, 0.f, 0.f);
        int e = e0;
        // ---- x8 unroll: 8 independent gathers in flight ----
        for (; e + 8 <= e1; e += 8) {
            int   si[8]; float wi[8]; uint2 ui[8];
#pragma unroll
            for (int q = 0; q < 8; q++) si[q] = __ldcs(g_csrsrc + e + q);
#pragma unroll
            for (int q = 0; q < 8; q++) wi[q] = __ldcs(g_csrw + e + q);
#pragma unroll
            for (int q = 0; q < 8; q++) ui[q] = hw2[(size_t)si[q] * 32 + lane];
#pragma unroll
            for (int q = 0; q < 8; q++) {
                float2 f0 = __half22float2(*(__half2*)&ui[q].x);
                float2 f1 = __half22float2(*(__half2*)&ui[q].y);
                acc.x = fmaf(wi[q], f0.x, acc.x);
                acc.y = fmaf(wi[q], f0.y, acc.y);
                acc.z = fmaf(wi[q], f1.x, acc.z);
                acc.w = fmaf(wi[q], f1.y, acc.w);
            }
        }
        // ---- x4 cleanup ----
        for (; e + 4 <= e1; e += 4) {
            int   si[4]; float wi[4]; uint2 ui[4];
#pragma unroll
            for (int q = 0; q < 4; q++) si[q] = __ldcs(g_csrsrc + e + q);
#pragma unroll
            for (int q = 0; q < 4; q++) wi[q] = __ldcs(g_csrw + e + q);
#pragma unroll
            for (int q = 0; q < 4; q++) ui[q] = hw2[(size_t)si[q] * 32 + lane];
#pragma unroll
            for (int q = 0; q < 4; q++) {
                float2 f0 = __half22float2(*(__half2*)&ui[q].x);
                float2 f1 = __half22float2(*(__half2*)&ui[q].y);
                acc.x = fmaf(wi[q], f0.x, acc.x);
                acc.y = fmaf(wi[q], f0.y, acc.y);
                acc.z = fmaf(wi[q], f1.x, acc.z);
                acc.w = fmaf(wi[q], f1.y, acc.w);
            }
        }
        // ---- remainder ----
        for (; e < e1; e++) {
            int   src = __ldcs(g_csrsrc + e);
            float wt  = __ldcs(g_csrw + e);
            uint2 u = hw2[(size_t)src * 32 + lane];
            float2 f0 = __half22float2(*(__half2*)&u.x);
            float2 f1 = __half22float2(*(__half2*)&u.y);
            acc.x = fmaf(wt, f0.x, acc.x);
            acc.y = fmaf(wt, f0.y, acc.y);
            acc.z = fmaf(wt, f1.x, acc.z);
            acc.w = fmaf(wt, f1.y, acc.w);
        }
        float di = g_dinv[w];
        float sn = di * di;                       // 1/deg (self-loop norm)
        uint2 su = hw2[(size_t)w * 32 + lane];
        float2 s0 = __half22float2(*(__half2*)&su.x);
        float2 s1 = __half22float2(*(__half2*)&su.y);
        acc.x = fmaf(sn, s0.x, acc.x) + bias[lane * 4 + 0];
        acc.y = fmaf(sn, s0.y, acc.y) + bias[lane * 4 + 1];
        acc.z = fmaf(sn, s1.x, acc.z) + bias[lane * 4 + 2];
        acc.w = fmaf(sn, s1.y, acc.w) + bias[lane * 4 + 3];
        ((float4*)OUT)[(size_t)w * 32 + lane] = acc;

        atomicAdd(&s_sum[lane * 4 + 0], acc.x);
        atomicAdd(&s_sum[lane * 4 + 1], acc.y);
        atomicAdd(&s_sum[lane * 4 + 2], acc.z);
        atomicAdd(&s_sum[lane * 4 + 3], acc.w);
        atomicAdd(&s_sq[lane * 4 + 0], acc.x * acc.x);
        atomicAdd(&s_sq[lane * 4 + 1], acc.y * acc.y);
        atomicAdd(&s_sq[lane * 4 + 2], acc.z * acc.z);
        atomicAdd(&s_sq[lane * 4 + 3], acc.w * acc.w);
    }
    __syncthreads();
    if (tid < H) {
        atomicAdd(&g_bnsum[layer * H + tid], s_sum[tid]);
        atomicAdd(&g_bnsq [layer * H + tid], s_sq[tid]);
    }

    // ---- last-block BN finalize (replaces k_bnfin launch) ----
    __shared__ int s_last;
    __threadfence();
    __syncthreads();
    if (tid == 0) {
        int prev = atomicAdd(&g_aggdone[layer], 1);
        s_last = (prev == gridDim.x - 1);
    }
    __syncthreads();
    if (s_last && tid < H) {
        float invN = 1.0f / (float)Nn;
        float mean = g_bnsum[layer * H + tid] * invN;
        float var  = g_bnsq [layer * H + tid] * invN - mean * mean;
        float inv  = rsqrtf(var + 1e-5f);
        float sc   = gammas[layer * H + tid] * inv;
        g_ts[(layer + 1) * H + tid] = sc;
        g_tt[(layer + 1) * H + tid] = betas[layer * H + tid] - mean * sc;
    }
}

// ---------------- fused pool + head MLP (256 thr: 2 row-groups per graph) ---------
__global__ void k_poolmlp(const float* __restrict__ P,
                          const float* __restrict__ W1, const float* __restrict__ b1,
                          const float* __restrict__ W2, const float* __restrict__ b2,
                          float* __restrict__ out) {
    __shared__ float p[H], t1[H], part[H];
    int g = blockIdx.x;
    int c = threadIdx.x & 127;
    int grp = threadIdx.x >> 7;                 // 0 or 1
    int a = g_gstart[g], b = g_gstart[g + 1];
    float sc = g_ts[LAYERS * H + c], tt = g_tt[LAYERS * H + c];
    float acc = 0.f;
    for (int r = a + grp; r < b; r += 2)
        acc += fmaxf(fmaf(P[(size_t)r * H + c], sc, tt), 0.f);
    if (grp == 1) part[c] = acc;
    __syncthreads();
    if (grp == 0) p[c] = (acc + part[c]) / fmaxf((float)(b - a), 1.0f);
    __syncthreads();

    if (grp == 0) {
        float h1 = b1[c];
#pragma unroll
        for (int k = 0; k < H; k++) h1 = fmaf(p[k], W1[k * H + c], h1);
        t1[c] = fmaxf(h1, 0.f);
    }
    __syncthreads();
    if (grp == 0 && c < EMB) {
        float o = b2[c];
#pragma unroll
        for (int k = 0; k < H; k++) o = fmaf(t1[k], W2[k * EMB + c], o);
        out[(size_t)g * EMB + c] = o;
    }
}

// ---------------- launch ----------------
extern "C" void kernel_launch(void* const* d_in, const int* in_sizes, int n_in,
                              void* d_out, int out_size)
{
    const float* x      = (const float*)d_in[0];
    const int*   ei     = (const int*)  d_in[1];
    const int*   batch  = (const int*)  d_in[2];
    const float* W_in   = (const float*)d_in[3];
    const float* b_in   = (const float*)d_in[4];
    const float* Ws     = (const float*)d_in[5];
    const float* bs     = (const float*)d_in[6];
    const float* gammas = (const float*)d_in[7];
    const float* betas  = (const float*)d_in[8];
    const float* W1     = (const float*)d_in[9];
    const float* b1     = (const float*)d_in[10];
    const float* W2     = (const float*)d_in[11];
    const float* b2     = (const float*)d_in[12];

    int Nn = in_sizes[0] / H;
    int E  = in_sizes[1] / 2;
    int G  = out_size / EMB;

    float *P, *ts, *tt;
    void* HWp;
    cudaGetSymbolAddress((void**)&P,   g_P);
    cudaGetSymbolAddress(&HWp,         g_HW);
    cudaGetSymbolAddress((void**)&ts,  g_ts);
    cudaGetSymbolAddress((void**)&tt,  g_tt);

    int mblocks = (Nn + MT - 1) / MT;
    int nb = (Nn + 1023) / 1024;

    // side stream + fork/join events (created once; capture-legal pattern)
    static cudaStream_t s_side = nullptr;
    static cudaEvent_t  ev_fork = nullptr, ev_join = nullptr;
    if (s_side == nullptr) {
        cudaStreamCreateWithFlags(&s_side, cudaStreamNonBlocking);
        cudaEventCreateWithFlags(&ev_fork, cudaEventDisableTiming);
        cudaEventCreateWithFlags(&ev_join, cudaEventDisableTiming);
    }

    // ---- fork: graph build on side stream, GEMMs on main stream ----
    cudaEventRecord(ev_fork, 0);
    cudaStreamWaitEvent(s_side, ev_fork, 0);

    k_init <<<(Nn + 255) / 256, 256, 0, s_side>>>(Nn);
    k_count<<<(E + 255) / 256, 256, 0, s_side>>>(ei, E);
    k_dinv <<<(Nn + 255) / 256, 256, 0, s_side>>>(Nn);

    // main stream: input projection + layer-0 transform GEMM (TRANSFORM=2: plain ReLU)
    k_gemm<0, 0><<<mblocks, 128>>>(x, W_in, P, Nn, nullptr, nullptr, b_in);
    k_gemm<2, 1><<<mblocks, 128>>>(P, Ws, HWp, Nn, nullptr, nullptr, nullptr);

    k_chunksum  <<<nb, 256, 0, s_side>>>(Nn);
    k_scanchunks<<<1, 32, 0, s_side>>>(nb);
    k_scanlocal <<<nb, 1024, 0, s_side>>>(Nn, E);
    k_scatter   <<<(E + 255) / 256, 256, 0, s_side>>>(ei, E);
    k_gstart    <<<(G + 256) / 256, 256, 0, s_side>>>(batch, Nn, G);

    // ---- join before first aggregation (needs CSR + dinv + zeroed BN sums) ----
    cudaEventRecord(ev_join, s_side);
    cudaStreamWaitEvent(0, ev_join, 0);

    int ablocks = (Nn * 32 + 255) / 256;
    for (int l = 0; l < LAYERS; l++) {
        if (l > 0)
            k_gemm<1, 1><<<mblocks, 128>>>(P, Ws + l * H * H, HWp, Nn,
                                           ts + l * H, tt + l * H, nullptr);
        k_agg<<<ablocks, 256>>>((const __half*)HWp, bs + l * H, P, Nn, l, gammas, betas);
    }

    k_poolmlp<<<G, 256>>>(P, W1, b1, W2, b2, (float*)d_out);
}